// round 4
// baseline (speedup 1.0000x reference)
#include <cuda_runtime.h>
#include <cfloat>

#define HW   (512*512)
#define W    512
#define NCH  48            // 16 batches * 3 channels
#define FW   23
#define PAD  11

#define MB   8192          // median histogram bins over [-8, 8), width 1/512
#define PB   8192          // pct histogram bins: i=(int)(res*256)+4096, res in (-16,16)
#define CAP  16384         // median candidate capacity per channel
#define SEG  8             // data-pass blocks per channel
#define WLO_BIN 4086       // median fast-path candidate window [WLO_BIN, WHI_BIN)
#define WHI_BIN 4106

// conv tiling
#define CTX  64
#define CTY  64
#define CSH  (CTX + 2*PAD)   // 86
#define CTHREADS 512

// scratch (no cudaMalloc allowed)
__device__ float    g_res[(size_t)NCH * HW];
__device__ unsigned g_mhist[NCH * MB];
__device__ unsigned g_phist[NCH * PB];
__device__ float    g_cand[NCH * CAP];
__device__ int      g_ccount[NCH];
__device__ int      g_selbin[NCH];
__device__ int      g_selrank[NCH];
__device__ int      g_fast[NCH];
__device__ float    g_med[NCH];
__device__ float    g_lo[NCH];
__device__ float    g_hi[NCH];
__device__ float    g_k1[FW];

// ---------------------------------------------------------------------------
__global__ void zero_kernel(const float* __restrict__ kern) {
    int i = blockIdx.x * blockDim.x + threadIdx.x;
    g_mhist[i] = 0;                 // grid sized exactly NCH*MB
    g_phist[i] = 0;                 // PB == MB
    if (i < NCH) g_ccount[i] = 0;
    if (blockIdx.x == 0 && threadIdx.x < FW) {
        float s = 0.0f;
        for (int j = 0; j < FW; j++) s += kern[threadIdx.x * FW + j];
        g_k1[threadIdx.x] = s;
    }
}

// ---------------------------------------------------------------------------
// block-wide exclusive scan over 1024 threads (shuffle-based)
// ---------------------------------------------------------------------------
__device__ __forceinline__ unsigned block_excl_scan_1024(unsigned val) {
    __shared__ unsigned warpsum[32];
    const unsigned lane = threadIdx.x & 31, wid = threadIdx.x >> 5;
    unsigned s = val;
    #pragma unroll
    for (int o = 1; o < 32; o <<= 1) {
        unsigned t = __shfl_up_sync(0xFFFFFFFFu, s, o);
        if (lane >= o) s += t;
    }
    if (lane == 31) warpsum[wid] = s;
    __syncthreads();
    if (wid == 0) {
        unsigned w = warpsum[lane];
        #pragma unroll
        for (int o = 1; o < 32; o <<= 1) {
            unsigned t = __shfl_up_sync(0xFFFFFFFFu, w, o);
            if (lane >= o) w += t;
        }
        warpsum[lane] = w;
    }
    __syncthreads();
    unsigned wexcl = wid ? warpsum[wid - 1] : 0u;
    return wexcl + s - val;
}

// ---------------------------------------------------------------------------
// median: value-binned histogram over [-8, 8), bin width 1/512
// ---------------------------------------------------------------------------
__device__ __forceinline__ int med_bin(float v) {
    int b = (int)floorf(fmaf(v, 512.0f, 4096.0f));
    return b < 0 ? 0 : (b > MB - 1 ? MB - 1 : b);
}

__global__ __launch_bounds__(512)
void med_hist(const float* __restrict__ x) {
    __shared__ unsigned sh[MB];                       // 32 KB
    const int ch = blockIdx.x / SEG, seg = blockIdx.x % SEG;
    const int tid = threadIdx.x;
    for (int i = tid; i < MB; i += 512) sh[i] = 0;
    __syncthreads();
    const float4* p = (const float4*)(x + (size_t)ch * HW) + (size_t)seg * (HW / 4 / SEG);
    for (int i = tid; i < HW / 4 / SEG; i += 512) {
        float4 v = p[i];
        float vv[4] = { v.x, v.y, v.z, v.w };
        #pragma unroll
        for (int j = 0; j < 4; j++) {
            int b = med_bin(vv[j]);
            atomicAdd(&sh[b], 1u);
            if (b >= WLO_BIN && b < WHI_BIN) {        // opportunistic candidate collect
                int pp = atomicAdd(&g_ccount[ch], 1);
                if (pp < CAP) g_cand[ch * CAP + pp] = vv[j];
            }
        }
    }
    __syncthreads();
    unsigned* gh = g_mhist + ch * MB;
    for (int i = tid; i < MB; i += 512) {
        unsigned c = sh[i];
        if (c) atomicAdd(&gh[i], c);
    }
}

__global__ __launch_bounds__(1024)
void med_scan() {
    const int ch = blockIdx.x, tid = threadIdx.x;
    const unsigned* h = g_mhist + ch * MB;
    __shared__ unsigned s_prefwlo;
    __shared__ int s_selbin, s_selrank;
    unsigned loc[MB / 1024];
    unsigned s = 0;
    #pragma unroll
    for (int j = 0; j < MB / 1024; j++) { loc[j] = h[tid * (MB / 1024) + j]; s += loc[j]; }
    unsigned pref = block_excl_scan_1024(s);
    if (tid == WLO_BIN / (MB / 1024)) {
        unsigned c = pref;
        for (int j = 0; j < WLO_BIN % (MB / 1024); j++) c += loc[j];
        s_prefwlo = c;
    }
    const unsigned k = (HW - 1) / 2;
    if (pref <= k && k < pref + s) {
        unsigned cum = pref;
        #pragma unroll
        for (int j = 0; j < MB / 1024; j++) {
            unsigned c = loc[j];
            if (cum + c > k) { s_selbin = tid * (MB / 1024) + j; s_selrank = (int)(k - cum); break; }
            cum += c;
        }
    }
    __syncthreads();
    if (tid == 0) {
        int cnt = g_ccount[ch];
        int fast = (s_selbin >= WLO_BIN && s_selbin < WHI_BIN && cnt <= CAP);
        g_fast[ch] = fast;
        if (fast) {
            g_selrank[ch] = (int)(k - s_prefwlo);     // rank within window candidates
        } else {
            g_selbin[ch]  = s_selbin;
            g_selrank[ch] = s_selrank;
            g_ccount[ch]  = 0;                        // refill in med_collect
        }
    }
}

__global__ __launch_bounds__(512)
void med_collect(const float* __restrict__ x) {
    const int ch = blockIdx.x / SEG, seg = blockIdx.x % SEG;
    if (g_fast[ch]) return;                           // fast path: already collected
    const int tid = threadIdx.x;
    const int sb = g_selbin[ch];
    const float4* p = (const float4*)(x + (size_t)ch * HW) + (size_t)seg * (HW / 4 / SEG);
    for (int i = tid; i < HW / 4 / SEG; i += 512) {
        float4 v = p[i];
        float vv[4] = { v.x, v.y, v.z, v.w };
        #pragma unroll
        for (int j = 0; j < 4; j++) {
            if (med_bin(vv[j]) == sb) {
                int pp = atomicAdd(&g_ccount[ch], 1);
                if (pp < CAP) g_cand[ch * CAP + pp] = vv[j];
            }
        }
    }
}

// exact selection among <=CAP candidates: minmax -> 8192 fine bins -> tiny rank
__global__ __launch_bounds__(1024)
void med_select() {
    const int ch = blockIdx.x, tid = threadIdx.x;
    __shared__ unsigned fh[8192];                     // 32 KB
    __shared__ float s_red[32];
    __shared__ float s_mn, s_mx;
    __shared__ int s_fb, s_r2;
    __shared__ float mem[512];
    __shared__ int mcount;

    int n = g_ccount[ch];
    if (n > CAP) n = CAP;
    const int k2 = g_selrank[ch];
    const float* c = g_cand + ch * CAP;

    // min/max reduce
    float mn = FLT_MAX, mx = -FLT_MAX;
    for (int i = tid; i < n; i += 1024) {
        float v = c[i];
        mn = fminf(mn, v); mx = fmaxf(mx, v);
    }
    for (int o = 16; o; o >>= 1) {
        mn = fminf(mn, __shfl_down_sync(0xFFFFFFFFu, mn, o));
        mx = fmaxf(mx, __shfl_down_sync(0xFFFFFFFFu, mx, o));
    }
    if ((tid & 31) == 0) s_red[tid >> 5] = mn;
    __syncthreads();
    if (tid < 32) {
        float v = s_red[tid];
        for (int o = 16; o; o >>= 1) v = fminf(v, __shfl_down_sync(0xFFFFFFFFu, v, o));
        if (tid == 0) s_mn = v;
    }
    __syncthreads();
    if ((tid & 31) == 0) s_red[tid >> 5] = mx;
    __syncthreads();
    if (tid < 32) {
        float v = s_red[tid];
        for (int o = 16; o; o >>= 1) v = fmaxf(v, __shfl_down_sync(0xFFFFFFFFu, v, o));
        if (tid == 0) s_mx = v;
    }
    __syncthreads();
    const float mnv = s_mn, mxv = s_mx;
    if (mnv == mxv) { if (tid == 0) g_med[ch] = mnv + 0.2f; return; }

    // fine histogram
    for (int i = tid; i < 8192; i += 1024) fh[i] = 0;
    __syncthreads();
    const float scale = 8192.0f / (mxv - mnv);
    for (int i = tid; i < n; i += 1024) {
        int b = (int)((c[i] - mnv) * scale);
        b = b < 0 ? 0 : (b > 8191 ? 8191 : b);
        atomicAdd(&fh[b], 1u);
    }
    __syncthreads();
    unsigned loc[8];
    unsigned s = 0;
    #pragma unroll
    for (int j = 0; j < 8; j++) { loc[j] = fh[tid * 8 + j]; s += loc[j]; }
    unsigned pref = block_excl_scan_1024(s);
    if (pref <= (unsigned)k2 && (unsigned)k2 < pref + s) {
        unsigned cum = pref;
        #pragma unroll
        for (int j = 0; j < 8; j++) {
            unsigned cc = loc[j];
            if (cum + cc > (unsigned)k2) { s_fb = tid * 8 + j; s_r2 = (int)(k2 - cum); break; }
            cum += cc;
        }
    }
    if (tid == 0) mcount = 0;
    __syncthreads();
    const int fb = s_fb, r2 = s_r2;
    for (int i = tid; i < n; i += 1024) {
        int b = (int)((c[i] - mnv) * scale);
        b = b < 0 ? 0 : (b > 8191 ? 8191 : b);
        if (b == fb) {
            int pp = atomicAdd(&mcount, 1);
            if (pp < 512) mem[pp] = c[i];
        }
    }
    __syncthreads();
    int m = mcount < 512 ? mcount : 512;
    for (int i = tid; i < m; i += 1024) {
        float vi = mem[i];
        int r = 0;
        for (int j = 0; j < m; j++) {
            float vj = mem[j];
            r += (vj < vi) || (vj == vi && j < i);
        }
        if (r == r2) g_med[ch] = vi + 0.2f;
    }
}

// ---------------------------------------------------------------------------
// separable conv, 64x64 tile, register-blocked (8 outputs / thread / pass)
// ---------------------------------------------------------------------------
__global__ __launch_bounds__(CTHREADS, 2)
void conv_kernel(const float* __restrict__ x, const float* __restrict__ mask) {
    extern __shared__ float dsm[];
    float* s_in  = dsm;                    // CSH * CSH
    float* s_tmp = dsm + CSH * CSH;        // CSH * CTX
    __shared__ float s_k[FW];

    const int tid = threadIdx.x;
    const int ch = blockIdx.z;
    const int nb = ch / 3;
    const int bx = blockIdx.x * CTX, by = blockIdx.y * CTY;

    if (tid < FW) s_k[tid] = g_k1[tid];

    const float* xc = x + (size_t)ch * HW;
    const float* mc = mask + (size_t)nb * HW;
    const float med = g_med[ch];

    for (int i = tid; i < CSH * CSH; i += CTHREADS) {
        int r = i / CSH, c = i % CSH;
        int gy = min(max(by - PAD + r, 0), 511);
        int gx = min(max(bx - PAD + c, 0), 511);
        float xv = xc[gy * W + gx];
        float mv = mc[gy * W + gx];
        s_in[r * CSH + c] = mv * xv + (1.0f - mv) * med;
    }
    __syncthreads();

    // horizontal: 86 rows x 8 groups of 8 outputs = 688 items
    for (int item = tid; item < CSH * (CTX / 8); item += CTHREADS) {
        int r = item / (CTX / 8), g = item % (CTX / 8);
        const float* row = s_in + r * CSH + g * 8;
        float in[30];
        #pragma unroll
        for (int j = 0; j < 30; j++) in[j] = row[j];
        float acc[8];
        #pragma unroll
        for (int m = 0; m < 8; m++) {
            float a = 0.0f;
            #pragma unroll
            for (int j = 0; j < FW; j++) a += in[m + j] * s_k[j];
            acc[m] = a;
        }
        #pragma unroll
        for (int m = 0; m < 8; m++) s_tmp[r * CTX + g * 8 + m] = acc[m];
    }
    __syncthreads();

    // vertical: 64 cols x 8 y-groups of 8 outputs = 512 items
    {
        const int xx = tid % CTX, y0 = (tid / CTX) * 8;
        float t[30];
        #pragma unroll
        for (int i = 0; i < 30; i++) t[i] = s_tmp[(y0 + i) * CTX + xx];
        float acc[8];
        #pragma unroll
        for (int m = 0; m < 8; m++) {
            float a = 0.0f;
            #pragma unroll
            for (int i = 0; i < FW; i++) a += t[m + i] * s_k[i];
            acc[m] = a;
        }
        float* rp = g_res + (size_t)ch * HW + (size_t)(by + y0) * W + bx + xx;
        #pragma unroll
        for (int m = 0; m < 8; m++) {
            float xp = s_in[(y0 + m + PAD) * CSH + (xx + PAD)];
            rp[m * W] = 4.0f * (xp - acc[m]);
        }
    }
}

// ---------------------------------------------------------------------------
// percentile: exact via integer-quantized histogram (temp = i/256), clamp +-16
// ---------------------------------------------------------------------------
__global__ __launch_bounds__(512)
void pct_hist() {
    __shared__ unsigned shp[PB];                      // 32 KB
    const int ch = blockIdx.x / SEG, seg = blockIdx.x % SEG;
    const int tid = threadIdx.x;
    for (int i = tid; i < PB; i += 512) shp[i] = 0;
    __syncthreads();
    const float4* p = (const float4*)(g_res + (size_t)ch * HW) + (size_t)seg * (HW / 4 / SEG);
    for (int i = tid; i < HW / 4 / SEG; i += 512) {
        float4 v = p[i];
        int b0 = (int)(v.x * 256.0f) + PB / 2; b0 = b0 < 0 ? 0 : (b0 > PB - 1 ? PB - 1 : b0);
        int b1 = (int)(v.y * 256.0f) + PB / 2; b1 = b1 < 0 ? 0 : (b1 > PB - 1 ? PB - 1 : b1);
        int b2 = (int)(v.z * 256.0f) + PB / 2; b2 = b2 < 0 ? 0 : (b2 > PB - 1 ? PB - 1 : b2);
        int b3 = (int)(v.w * 256.0f) + PB / 2; b3 = b3 < 0 ? 0 : (b3 > PB - 1 ? PB - 1 : b3);
        atomicAdd(&shp[b0], 1u);
        atomicAdd(&shp[b1], 1u);
        atomicAdd(&shp[b2], 1u);
        atomicAdd(&shp[b3], 1u);
    }
    __syncthreads();
    unsigned* gh = g_phist + ch * PB;
    for (int i = tid; i < PB; i += 512) {
        unsigned c = shp[i];
        if (c) atomicAdd(&gh[i], c);
    }
}

__global__ __launch_bounds__(1024)
void pct_scan() {
    const int ch = blockIdx.x, tid = threadIdx.x;
    const unsigned* h = g_phist + ch * PB;
    unsigned loc[PB / 1024];
    unsigned s = 0;
    #pragma unroll
    for (int j = 0; j < PB / 1024; j++) { loc[j] = h[tid * (PB / 1024) + j]; s += loc[j]; }
    unsigned pref = block_excl_scan_1024(s);

    const double n1 = (double)(HW - 1);
    #pragma unroll
    for (int rsel = 0; rsel < 2; rsel++) {
        double pos = n1 * (rsel ? 0.97 : 0.03);
        unsigned k = (unsigned)pos;
        float fr = (float)(pos - (double)k);
        if (pref <= k && k < pref + s) {
            unsigned cum = pref;
            #pragma unroll
            for (int j = 0; j < PB / 1024; j++) {
                unsigned c = loc[j];
                int b = tid * (PB / 1024) + j;
                if (cum + c > k) {
                    float v = (float)(b - PB / 2) * (1.0f / 256.0f);
                    float v1 = v;
                    if (k + 1 >= cum + c) {               // next value in a later bin
                        int b2 = b + 1;
                        while (b2 < PB && h[b2] == 0) b2++;
                        if (b2 < PB) v1 = (float)(b2 - PB / 2) * (1.0f / 256.0f);
                    }
                    float out = v + fr * (v1 - v);
                    if (rsel) g_hi[ch] = out; else g_lo[ch] = out;
                    break;
                }
                cum += c;
            }
        }
    }
}

// ---------------------------------------------------------------------------
__global__ void final_kernel(const float* __restrict__ mask, float* __restrict__ out) {
    const int ch = blockIdx.y;
    const int nb = ch / 3;
    const int i = blockIdx.x * blockDim.x + threadIdx.x;   // float4 index
    const float lo = g_lo[ch], hi = g_hi[ch];
    const float inv = 1.0f / (hi - lo);
    float4 r = ((const float4*)(g_res + (size_t)ch * HW))[i];
    float4 m = ((const float4*)(mask + (size_t)nb * HW))[i];
    float4 o;
    o.x = (r.x - lo) * inv * m.x;
    o.y = (r.y - lo) * inv * m.y;
    o.z = (r.z - lo) * inv * m.z;
    o.w = (r.w - lo) * inv * m.w;
    ((float4*)out)[(size_t)ch * (HW / 4) + i] = o;
}

// ---------------------------------------------------------------------------
extern "C" void kernel_launch(void* const* d_in, const int* in_sizes, int n_in,
                              void* d_out, int out_size) {
    const float* x    = (const float*)d_in[0];
    const float* mask = (const float*)d_in[1];
    const float* kern = (const float*)d_in[2];
    float* out = (float*)d_out;

    cudaFuncSetAttribute(conv_kernel, cudaFuncAttributeMaxDynamicSharedMemorySize,
                         (CSH * CSH + CSH * CTX) * 4);

    zero_kernel<<<NCH * MB / 1024, 1024>>>(kern);
    med_hist<<<NCH * SEG, 512>>>(x);
    med_scan<<<NCH, 1024>>>();
    med_collect<<<NCH * SEG, 512>>>(x);
    med_select<<<NCH, 1024>>>();
    conv_kernel<<<dim3(W / CTX, W / CTY, NCH), CTHREADS, (CSH * CSH + CSH * CTX) * 4>>>(x, mask);
    pct_hist<<<NCH * SEG, 512>>>();
    pct_scan<<<NCH, 1024>>>();
    final_kernel<<<dim3(HW / 4 / 256, NCH), 256>>>(mask, out);
}